// round 2
// baseline (speedup 1.0000x reference)
#include <cuda_runtime.h>

#define B_   4
#define N_   4096
#define FIN  256
#define FOUT 128
#define MTOT (B_ * N_)   // 16384

// Scratch (allocation-free rule: __device__ globals)
__device__ float g_Wh[(size_t)MTOT * FOUT];   // 8 MB
__device__ float g_src[MTOT];
__device__ float g_dst[MTOT];

// ---------- packed fp32x2 helpers (sm_10x) ----------
__device__ __forceinline__ unsigned long long pk2(float x) {
    unsigned long long r;
    asm("mov.b64 %0, {%1, %1};" : "=l"(r) : "f"(x));
    return r;
}
__device__ __forceinline__ void ffma2(unsigned long long& d,
                                      unsigned long long a,
                                      unsigned long long b) {
    asm("fma.rn.f32x2 %0, %1, %2, %0;" : "+l"(d) : "l"(a), "l"(b));
}
__device__ __forceinline__ float2 up2(unsigned long long v) {
    float2 f;
    asm("mov.b64 {%0, %1}, %2;" : "=f"(f.x), "=f"(f.y) : "l"(v));
    return f;
}

// ============================================================
// Kernel 1: Wh = h @ W^T + b   (M=16384, N=128, K=256)
// Also fuses src = Wh·a_src, dst = Wh·a_dst per row.
// Block: 64 rows x 128 cols, 256 threads, 4x8 per thread.
// ============================================================
__global__ void __launch_bounds__(256) k_gemm(
    const float* __restrict__ h, const float* __restrict__ Ww,
    const float* __restrict__ Wb, const float* __restrict__ aw)
{
    __shared__ float hs[32][68];    // [k][i], padded
    __shared__ float ws[32][132];   // [k][o], padded

    const int t  = threadIdx.x;
    const int r0 = blockIdx.x * 64;
    const int to = t & 15, ti = t >> 4;
    const int i0 = ti * 4, o0 = to * 4;   // this thread: rows i0..i0+3, cols {o0..o0+3, 64+o0..64+o0+3}

    float acc[4][8];
#pragma unroll
    for (int a = 0; a < 4; a++)
#pragma unroll
        for (int c = 0; c < 8; c++) acc[a][c] = 0.f;

    const int hi = t >> 2, hkb = (t & 3) * 8;   // h tile loader map
    const int wo = t >> 1, wkb = (t & 1) * 16;  // W tile loader map

    for (int kt = 0; kt < FIN; kt += 32) {
        const float* hp = h + (size_t)(r0 + hi) * FIN + kt + hkb;
        float4 ha = *(const float4*)(hp);
        float4 hb = *(const float4*)(hp + 4);
        const float* wp = Ww + (size_t)wo * FIN + kt + wkb;
        float4 wa  = *(const float4*)(wp);
        float4 wb4 = *(const float4*)(wp + 4);
        float4 wc  = *(const float4*)(wp + 8);
        float4 wd  = *(const float4*)(wp + 12);

        __syncthreads();   // previous tile's compute done

        hs[hkb + 0][hi] = ha.x; hs[hkb + 1][hi] = ha.y;
        hs[hkb + 2][hi] = ha.z; hs[hkb + 3][hi] = ha.w;
        hs[hkb + 4][hi] = hb.x; hs[hkb + 5][hi] = hb.y;
        hs[hkb + 6][hi] = hb.z; hs[hkb + 7][hi] = hb.w;

        ws[wkb +  0][wo] = wa.x;  ws[wkb +  1][wo] = wa.y;
        ws[wkb +  2][wo] = wa.z;  ws[wkb +  3][wo] = wa.w;
        ws[wkb +  4][wo] = wb4.x; ws[wkb +  5][wo] = wb4.y;
        ws[wkb +  6][wo] = wb4.z; ws[wkb +  7][wo] = wb4.w;
        ws[wkb +  8][wo] = wc.x;  ws[wkb +  9][wo] = wc.y;
        ws[wkb + 10][wo] = wc.z;  ws[wkb + 11][wo] = wc.w;
        ws[wkb + 12][wo] = wd.x;  ws[wkb + 13][wo] = wd.y;
        ws[wkb + 14][wo] = wd.z;  ws[wkb + 15][wo] = wd.w;

        __syncthreads();

#pragma unroll 8
        for (int kk = 0; kk < 32; kk++) {
            float4 a4 = *(const float4*)&hs[kk][i0];
            float4 b0 = *(const float4*)&ws[kk][o0];
            float4 b1 = *(const float4*)&ws[kk][o0 + 64];
            float av[4] = {a4.x, a4.y, a4.z, a4.w};
            float bv[8] = {b0.x, b0.y, b0.z, b0.w, b1.x, b1.y, b1.z, b1.w};
#pragma unroll
            for (int ii = 0; ii < 4; ii++)
#pragma unroll
                for (int oo = 0; oo < 8; oo++)
                    acc[ii][oo] = fmaf(av[ii], bv[oo], acc[ii][oo]);
        }
    }

    // epilogue: bias, store Wh, fused src/dst dot products
    float bo[8], asv[8], adv[8];
#pragma unroll
    for (int oo = 0; oo < 8; oo++) {
        int o = (oo < 4) ? (o0 + oo) : (64 + o0 + oo - 4);
        bo[oo]  = Wb[o];
        asv[oo] = aw[o];
        adv[oo] = aw[FOUT + o];
    }
    float sp[4], dp[4];
#pragma unroll
    for (int ii = 0; ii < 4; ii++) {
        float s = 0.f, d = 0.f;
#pragma unroll
        for (int oo = 0; oo < 8; oo++) {
            float v = acc[ii][oo] + bo[oo];
            acc[ii][oo] = v;
            s = fmaf(v, asv[oo], s);
            d = fmaf(v, adv[oo], d);
        }
        sp[ii] = s; dp[ii] = d;
        const int row = r0 + i0 + ii;
        *(float4*)&g_Wh[(size_t)row * FOUT + o0] =
            make_float4(acc[ii][0], acc[ii][1], acc[ii][2], acc[ii][3]);
        *(float4*)&g_Wh[(size_t)row * FOUT + 64 + o0] =
            make_float4(acc[ii][4], acc[ii][5], acc[ii][6], acc[ii][7]);
    }
    // reduce src/dst partials across the 16 o-threads (16 consecutive lanes)
#pragma unroll
    for (int off = 8; off >= 1; off >>= 1)
#pragma unroll
        for (int ii = 0; ii < 4; ii++) {
            sp[ii] += __shfl_down_sync(0xffffffffu, sp[ii], off);
            dp[ii] += __shfl_down_sync(0xffffffffu, dp[ii], off);
        }
    if (to == 0)
#pragma unroll
        for (int ii = 0; ii < 4; ii++) {
            g_src[r0 + i0 + ii] = sp[ii];
            g_dst[r0 + i0 + ii] = dp[ii];
        }
}

// ============================================================
// Kernel 2: masked-softmax aggregation.
// out[i,:] = (sum_j adj_ij * exp(lrelu(src_i+dst_j+ab)) * Wh[j,:]) / den_i
// No row-max needed: e is bounded (|e| < ~15), exp() can't overflow fp32,
// and softmax is shift-invariant so results match the reference.
// Block = 64 rows; j-tiles of 32; 4x8 per thread; f32x2 packed FMA.
// ============================================================
__global__ void __launch_bounds__(256, 2) k_attn(
    const int* __restrict__ adj, const float* __restrict__ abp,
    float* __restrict__ out)
{
    __shared__ float w_s[32][68];     // [j][i] exp weights, padded
    __shared__ float v_s[32][128];    // [j][o] Wh tile
    __shared__ float src_s[64];
    __shared__ float den_s[64];

    const int t   = threadIdx.x;
    const int rg0 = blockIdx.x * 64;        // global row base (batch-aligned: 64 | 4096)
    const int bN  = (rg0 >> 12) << 12;      // batch row offset
    const float ab = *abp;

    if (t < 64) src_s[t] = g_src[rg0 + t];
    __syncthreads();

    const int to = t & 15, ti = t >> 4;
    const int i0 = ti * 4, o0 = to * 4;
    const int ai = t >> 2, ajb = (t & 3) * 8;   // weight-producer map: row ai, 8 j's
    const int vj = t >> 3, vc = (t & 7) * 16;   // Wh-tile loader map

    const float srcA = src_s[ai] + ab;
    const int*   adj_row = adj + (size_t)(rg0 + ai) * N_;
    const float* vrow    = g_Wh + (size_t)(bN + vj) * FOUT + vc;
    const float* drow    = g_dst + bN + ajb;

    unsigned long long acc2[4][4];
#pragma unroll
    for (int a = 0; a < 4; a++)
#pragma unroll
        for (int c = 0; c < 4; c++) acc2[a][c] = 0ull;
    float denp = 0.f;

    for (int jt = 0; jt < N_ / 32; jt++) {
        const int j0 = jt * 32;
        // global stage -> registers (overlap adj + Wh latency)
        float4 v0 = *(const float4*)(vrow + (size_t)j0 * FOUT);
        float4 v1 = *(const float4*)(vrow + (size_t)j0 * FOUT + 4);
        float4 v2 = *(const float4*)(vrow + (size_t)j0 * FOUT + 8);
        float4 v3 = *(const float4*)(vrow + (size_t)j0 * FOUT + 12);
        int4 m0 = *(const int4*)(adj_row + j0 + ajb);
        int4 m1 = *(const int4*)(adj_row + j0 + ajb + 4);
        float4 d0 = *(const float4*)(drow + j0);
        float4 d1 = *(const float4*)(drow + j0 + 4);

        int   mm[8] = {m0.x, m0.y, m0.z, m0.w, m1.x, m1.y, m1.z, m1.w};
        float dd[8] = {d0.x, d0.y, d0.z, d0.w, d1.x, d1.y, d1.z, d1.w};
        float wv[8];
#pragma unroll
        for (int u = 0; u < 8; u++) {
            float e = srcA + dd[u];
            e = (e >= 0.f) ? e : 0.01f * e;
            float w = (mm[u] > 0) ? __expf(e) : 0.f;
            wv[u] = w;
            denp += w;          // den accumulated in cheap phase
        }

        __syncthreads();        // previous tile's consumers done
#pragma unroll
        for (int u = 0; u < 8; u++) w_s[ajb + u][ai] = wv[u];
        *(float4*)&v_s[vj][vc]      = v0;
        *(float4*)&v_s[vj][vc + 4]  = v1;
        *(float4*)&v_s[vj][vc + 8]  = v2;
        *(float4*)&v_s[vj][vc + 12] = v3;
        __syncthreads();

#pragma unroll 8
        for (int j = 0; j < 32; j++) {
            float4 w4 = *(const float4*)&w_s[j][i0];
            ulonglong2 va = *(const ulonglong2*)&v_s[j][o0];
            ulonglong2 vb = *(const ulonglong2*)&v_s[j][o0 + 64];
            float wc4[4] = {w4.x, w4.y, w4.z, w4.w};
#pragma unroll
            for (int ii = 0; ii < 4; ii++) {
                unsigned long long wp = pk2(wc4[ii]);
                ffma2(acc2[ii][0], wp, va.x);
                ffma2(acc2[ii][1], wp, va.y);
                ffma2(acc2[ii][2], wp, vb.x);
                ffma2(acc2[ii][3], wp, vb.y);
            }
        }
    }

    // den: 4 producer threads per row -> reduce within their 4 consecutive lanes
    denp += __shfl_down_sync(0xffffffffu, denp, 2);
    denp += __shfl_down_sync(0xffffffffu, denp, 1);
    if ((t & 3) == 0) den_s[ai] = denp;
    __syncthreads();

#pragma unroll
    for (int ii = 0; ii < 4; ii++) {
        const int row = rg0 + i0 + ii;
        const float inv = 1.0f / den_s[i0 + ii];
        float2 p0 = up2(acc2[ii][0]);
        float2 p1 = up2(acc2[ii][1]);
        float2 p2 = up2(acc2[ii][2]);
        float2 p3 = up2(acc2[ii][3]);
        *(float4*)&out[(size_t)row * FOUT + o0] =
            make_float4(p0.x * inv, p0.y * inv, p1.x * inv, p1.y * inv);
        *(float4*)&out[(size_t)row * FOUT + 64 + o0] =
            make_float4(p2.x * inv, p2.y * inv, p3.x * inv, p3.y * inv);
    }
}

extern "C" void kernel_launch(void* const* d_in, const int* in_sizes, int n_in,
                              void* d_out, int out_size) {
    const float* h   = (const float*)d_in[0];
    const int*   adj = (const int*)d_in[1];
    const float* Ww  = (const float*)d_in[2];
    const float* Wb  = (const float*)d_in[3];
    const float* aw  = (const float*)d_in[4];
    const float* abp = (const float*)d_in[5];
    float* outp = (float*)d_out;

    k_gemm<<<MTOT / 64, 256>>>(h, Ww, Wb, aw);
    k_attn<<<MTOT / 64, 256>>>(adj, abp, outp);
}

// round 4
// speedup vs baseline: 2.1320x; 2.1320x over previous
#include <cuda_runtime.h>
#include <cstdint>

#define B_   4
#define N_   4096
#define FIN  256
#define FOUT 128
#define MTOT (B_ * N_)   // 16384

// ---------------- device scratch (no-alloc rule) ----------------
__device__ float g_Wh[(size_t)MTOT * FOUT];   // tf32-rounded values, [row][o]
__device__ float g_src[MTOT];
__device__ float g_dst[MTOT];

// ---------------- helpers ----------------
__device__ __forceinline__ uint32_t f2tf32(float v) {
    uint32_t r;
    asm("cvt.rna.tf32.f32 %0, %1;" : "=r"(r) : "f"(v));
    return r;
}
__device__ __forceinline__ void mma_tf32(float* d, const uint32_t* a, const uint32_t* b) {
    asm volatile(
        "mma.sync.aligned.m16n8k8.row.col.f32.tf32.tf32.f32 "
        "{%0,%1,%2,%3}, {%4,%5,%6,%7}, {%8,%9}, {%0,%1,%2,%3};"
        : "+f"(d[0]), "+f"(d[1]), "+f"(d[2]), "+f"(d[3])
        : "r"(a[0]), "r"(a[1]), "r"(a[2]), "r"(a[3]), "r"(b[0]), "r"(b[1]));
}

// ============================================================
// Kernel 1: Wh = h @ W^T + b ; store tf32-rounded Wh + src/dst
// ============================================================
__global__ void __launch_bounds__(256) k_gemm(
    const float* __restrict__ h, const float* __restrict__ Ww,
    const float* __restrict__ Wb, const float* __restrict__ aw)
{
    __shared__ float hs[32][68];
    __shared__ float ws[32][132];

    const int t  = threadIdx.x;
    const int r0 = blockIdx.x * 64;
    const int to = t & 15, ti = t >> 4;
    const int i0 = ti * 4, o0 = to * 4;

    float acc[4][8];
#pragma unroll
    for (int a = 0; a < 4; a++)
#pragma unroll
        for (int c = 0; c < 8; c++) acc[a][c] = 0.f;

    const int hi = t >> 2, hkb = (t & 3) * 8;
    const int wo = t >> 1, wkb = (t & 1) * 16;

    for (int kt = 0; kt < FIN; kt += 32) {
        const float* hp = h + (size_t)(r0 + hi) * FIN + kt + hkb;
        float4 ha = *(const float4*)(hp);
        float4 hb = *(const float4*)(hp + 4);
        const float* wp = Ww + (size_t)wo * FIN + kt + wkb;
        float4 wa  = *(const float4*)(wp);
        float4 wb4 = *(const float4*)(wp + 4);
        float4 wc  = *(const float4*)(wp + 8);
        float4 wd  = *(const float4*)(wp + 12);

        __syncthreads();

        hs[hkb + 0][hi] = ha.x; hs[hkb + 1][hi] = ha.y;
        hs[hkb + 2][hi] = ha.z; hs[hkb + 3][hi] = ha.w;
        hs[hkb + 4][hi] = hb.x; hs[hkb + 5][hi] = hb.y;
        hs[hkb + 6][hi] = hb.z; hs[hkb + 7][hi] = hb.w;

        ws[wkb +  0][wo] = wa.x;  ws[wkb +  1][wo] = wa.y;
        ws[wkb +  2][wo] = wa.z;  ws[wkb +  3][wo] = wa.w;
        ws[wkb +  4][wo] = wb4.x; ws[wkb +  5][wo] = wb4.y;
        ws[wkb +  6][wo] = wb4.z; ws[wkb +  7][wo] = wb4.w;
        ws[wkb +  8][wo] = wc.x;  ws[wkb +  9][wo] = wc.y;
        ws[wkb + 10][wo] = wc.z;  ws[wkb + 11][wo] = wc.w;
        ws[wkb + 12][wo] = wd.x;  ws[wkb + 13][wo] = wd.y;
        ws[wkb + 14][wo] = wd.z;  ws[wkb + 15][wo] = wd.w;

        __syncthreads();

#pragma unroll 8
        for (int kk = 0; kk < 32; kk++) {
            float4 a4 = *(const float4*)&hs[kk][i0];
            float4 b0 = *(const float4*)&ws[kk][o0];
            float4 b1 = *(const float4*)&ws[kk][o0 + 64];
            float av[4] = {a4.x, a4.y, a4.z, a4.w};
            float bv[8] = {b0.x, b0.y, b0.z, b0.w, b1.x, b1.y, b1.z, b1.w};
#pragma unroll
            for (int ii = 0; ii < 4; ii++)
#pragma unroll
                for (int oo = 0; oo < 8; oo++)
                    acc[ii][oo] = fmaf(av[ii], bv[oo], acc[ii][oo]);
        }
    }

    float bo[8], asv[8], adv[8];
#pragma unroll
    for (int oo = 0; oo < 8; oo++) {
        int o = (oo < 4) ? (o0 + oo) : (64 + o0 + oo - 4);
        bo[oo]  = Wb[o];
        asv[oo] = aw[o];
        adv[oo] = aw[FOUT + o];
    }
    float sp[4], dp[4];
#pragma unroll
    for (int ii = 0; ii < 4; ii++) {
        float s = 0.f, d = 0.f;
        float v[8];
#pragma unroll
        for (int oo = 0; oo < 8; oo++) {
            v[oo] = acc[ii][oo] + bo[oo];
            s = fmaf(v[oo], asv[oo], s);
            d = fmaf(v[oo], adv[oo], d);
        }
        sp[ii] = s; dp[ii] = d;
        const int row = r0 + i0 + ii;
        *(float4*)&g_Wh[(size_t)row * FOUT + o0] =
            make_float4(__uint_as_float(f2tf32(v[0])), __uint_as_float(f2tf32(v[1])),
                        __uint_as_float(f2tf32(v[2])), __uint_as_float(f2tf32(v[3])));
        *(float4*)&g_Wh[(size_t)row * FOUT + 64 + o0] =
            make_float4(__uint_as_float(f2tf32(v[4])), __uint_as_float(f2tf32(v[5])),
                        __uint_as_float(f2tf32(v[6])), __uint_as_float(f2tf32(v[7])));
    }
#pragma unroll
    for (int off = 8; off >= 1; off >>= 1)
#pragma unroll
        for (int ii = 0; ii < 4; ii++) {
            sp[ii] += __shfl_down_sync(0xffffffffu, sp[ii], off);
            dp[ii] += __shfl_down_sync(0xffffffffu, dp[ii], off);
        }
    if (to == 0)
#pragma unroll
        for (int ii = 0; ii < 4; ii++) {
            g_src[r0 + i0 + ii] = sp[ii];
            g_dst[r0 + i0 + ii] = dp[ii];
        }
}

// ============================================================
// Kernel 2: attention via warp-level tf32 mma.sync.
// CTA: 128 rows x 128 cols, K-chunks of 64, 8 warps of 64x32 tiles.
// ============================================================
#define KC    64
#define STRD  136                         // smem row stride (floats): conflict-free fragments
#define SM_DST 0                          // 4096 f
#define SM_DEN 16384                      // 256 f
#define SM_A   17408                      // KC*STRD f  (A: [k][m], tf32 weights)
#define SM_B   (17408 + KC*STRD*4)        // KC*STRD f  (B: [k][o], tf32 Wh)
#define SMEM_SZ (SM_B + KC*STRD*4)

__global__ void __launch_bounds__(256, 1) k_attn(
    const int* __restrict__ adj, const float* __restrict__ abp,
    float* __restrict__ out)
{
    extern __shared__ char sm[];
    float*    dst_s = (float*)(sm + SM_DST);
    float*    den_s = (float*)(sm + SM_DEN);
    uint32_t* As    = (uint32_t*)(sm + SM_A);
    uint32_t* Bs    = (uint32_t*)(sm + SM_B);

    const int t   = threadIdx.x;
    const int rg0 = blockIdx.x * 128;
    const int b   = rg0 >> 12;
    const int bN  = b << 12;

    // stage dst for this batch
    {
        const float4* g  = (const float4*)(g_dst + bN);
        float4*       d4 = (float4*)dst_s;
        for (int q = t; q < N_ / 4; q += 256) d4[q] = g[q];
    }
    __syncthreads();

    // producer mapping: thread t -> row i, j-half
    const int i    = t & 127;
    const int half = t >> 7;               // 0/1 -> j offset 0/32
    const float srcA = g_src[rg0 + i] + *abp;
    const int* adjp = adj + (size_t)(rg0 + i) * N_ + half * 32;

    // B copy mapping: thread t -> Wh row (t>>2), float4 cols (t&3) + 4q
    const int bj = t >> 2, bc = t & 3;
    const float4* whp = (const float4*)(g_Wh + (size_t)(bN + bj) * FOUT) + bc;

    // mma mapping
    const int w = t >> 5, lane = t & 31;
    const int m0 = (w >> 2) * 64, n0 = (w & 3) * 32;
    const int lr = lane >> 2, lq = lane & 3;

    float acc[16][4];
#pragma unroll
    for (int x = 0; x < 16; x++)
#pragma unroll
        for (int y = 0; y < 4; y++) acc[x][y] = 0.f;
    float denp = 0.f;

    // prefetch chunk 0
    int4   mA[8];
    float4 vB[8];
#pragma unroll
    for (int q = 0; q < 8; q++) mA[q] = ((const int4*)adjp)[q];
#pragma unroll
    for (int q = 0; q < 8; q++) vB[q] = whp[q * 4];

    for (int c = 0; c < N_ / KC; c++) {
        // ---- weights: exp(lrelu(src+dst+ab)), masked; den in fp32 ----
        uint32_t wv[32];
#pragma unroll
        for (int q = 0; q < 8; q++) {
            float4 dv = *(const float4*)&dst_s[c * KC + half * 32 + q * 4];
            int4 m = mA[q];
            float e0 = srcA + dv.x, e1 = srcA + dv.y, e2 = srcA + dv.z, e3 = srcA + dv.w;
            e0 = (e0 >= 0.f) ? e0 : 0.01f * e0;
            e1 = (e1 >= 0.f) ? e1 : 0.01f * e1;
            e2 = (e2 >= 0.f) ? e2 : 0.01f * e2;
            e3 = (e3 >= 0.f) ? e3 : 0.01f * e3;
            float w0 = (m.x > 0) ? __expf(e0) : 0.f;
            float w1 = (m.y > 0) ? __expf(e1) : 0.f;
            float w2 = (m.z > 0) ? __expf(e2) : 0.f;
            float w3 = (m.w > 0) ? __expf(e3) : 0.f;
            denp += (w0 + w1) + (w2 + w3);
            wv[q * 4 + 0] = f2tf32(w0);
            wv[q * 4 + 1] = f2tf32(w1);
            wv[q * 4 + 2] = f2tf32(w2);
            wv[q * 4 + 3] = f2tf32(w3);
        }

        __syncthreads();   // previous chunk's mma reads done

        // ---- store A (weights) [k][m] and B (Wh) [k][o] ----
#pragma unroll
        for (int q = 0; q < 8; q++) {
            int k0 = half * 32 + q * 4;
            As[(k0 + 0) * STRD + i] = wv[q * 4 + 0];
            As[(k0 + 1) * STRD + i] = wv[q * 4 + 1];
            As[(k0 + 2) * STRD + i] = wv[q * 4 + 2];
            As[(k0 + 3) * STRD + i] = wv[q * 4 + 3];
        }
#pragma unroll
        for (int q = 0; q < 8; q++)
            *(float4*)&Bs[bj * STRD + (bc + 4 * q) * 4] = vB[q];

        // ---- prefetch next chunk (lands during mma) ----
        if (c < N_ / KC - 1) {
#pragma unroll
            for (int q = 0; q < 8; q++) mA[q] = ((const int4*)(adjp + (c + 1) * KC))[q];
#pragma unroll
            for (int q = 0; q < 8; q++) vB[q] = whp[((size_t)(c + 1) * KC) * (FOUT / 4) + q * 4];
        }

        __syncthreads();

        // ---- mma: 8 k-steps of m16n8k8 ----
#pragma unroll
        for (int kk = 0; kk < 8; kk++) {
            uint32_t bf[4][2];
#pragma unroll
            for (int nt = 0; nt < 4; nt++) {
                int o = n0 + nt * 8 + lr;
                bf[nt][0] = Bs[(kk * 8 + lq) * STRD + o];
                bf[nt][1] = Bs[(kk * 8 + lq + 4) * STRD + o];
            }
#pragma unroll
            for (int mt = 0; mt < 4; mt++) {
                uint32_t af[4];
                int m = m0 + mt * 16 + lr;
                af[0] = As[(kk * 8 + lq) * STRD + m];
                af[1] = As[(kk * 8 + lq) * STRD + m + 8];
                af[2] = As[(kk * 8 + lq + 4) * STRD + m];
                af[3] = As[(kk * 8 + lq + 4) * STRD + m + 8];
#pragma unroll
                for (int nt = 0; nt < 4; nt++)
                    mma_tf32(acc[mt * 4 + nt], af, bf[nt]);
            }
        }
    }

    den_s[t] = denp;
    __syncthreads();

    // ---- epilogue: divide by den, store ----
#pragma unroll
    for (int mt = 0; mt < 4; mt++) {
        int r0 = m0 + mt * 16 + lr;
        float inv0 = 1.0f / (den_s[r0] + den_s[r0 + 128]);
        float inv1 = 1.0f / (den_s[r0 + 8] + den_s[r0 + 8 + 128]);
        float* op0 = out + (size_t)(rg0 + r0) * FOUT;
        float* op1 = out + (size_t)(rg0 + r0 + 8) * FOUT;
#pragma unroll
        for (int nt = 0; nt < 4; nt++) {
            int col = n0 + nt * 8 + lq * 2;
            *(float2*)(op0 + col) = make_float2(acc[mt * 4 + nt][0] * inv0,
                                                acc[mt * 4 + nt][1] * inv0);
            *(float2*)(op1 + col) = make_float2(acc[mt * 4 + nt][2] * inv1,
                                                acc[mt * 4 + nt][3] * inv1);
        }
    }
}

extern "C" void kernel_launch(void* const* d_in, const int* in_sizes, int n_in,
                              void* d_out, int out_size) {
    const float* h   = (const float*)d_in[0];
    const int*   adj = (const int*)d_in[1];
    const float* Ww  = (const float*)d_in[2];
    const float* Wb  = (const float*)d_in[3];
    const float* aw  = (const float*)d_in[4];
    const float* abp = (const float*)d_in[5];
    float* outp = (float*)d_out;

    cudaFuncSetAttribute(k_attn, cudaFuncAttributeMaxDynamicSharedMemorySize, SMEM_SZ);

    k_gemm<<<MTOT / 64, 256>>>(h, Ww, Wb, aw);
    k_attn<<<MTOT / 128, 256, SMEM_SZ>>>(adj, abp, outp);
}